// round 5
// baseline (speedup 1.0000x reference)
#include <cuda_runtime.h>

// MaxUnpooling2D: updates [8,128,128,128] f32, mask [8,128,128,128] i32
// -> out [8,256,256,128] f32.
//
// mask = (y*WOUT + x)*C + f with y=2h+dy, x=2w+dx -> dy=(m>>15)&1, dx=(m>>7)&1.
// Each input element owns its 2x2 output window at its channel: value to (dy,dx),
// zeros to the other 3. Duplicate-free -> no atomics, no init pass, every output
// byte written exactly once.
//
// R4: 256-bit ld/st (Blackwell ld/st.global.v8.f32). One thread = 8 consecutive
// channels: 2x LDG.256 in, 4x STG.256 out. Halves request count at fixed bytes
// to probe whether LTS request efficiency is part of the 75%-of-HBM gap.

#define B_    8
#define H_    128
#define W_    128
#define C_    128
#define HOUT_ 256
#define WOUT_ 256

// threads = B*H*W*(C/8) = 2,097,152
#define NTHREADS_ (B_ * H_ * W_ * (C_ / 8))

__device__ __forceinline__ void ldg_v8(const float* __restrict__ p, float r[8])
{
    asm volatile("ld.global.v8.f32 {%0,%1,%2,%3,%4,%5,%6,%7}, [%8];"
                 : "=f"(r[0]), "=f"(r[1]), "=f"(r[2]), "=f"(r[3]),
                   "=f"(r[4]), "=f"(r[5]), "=f"(r[6]), "=f"(r[7])
                 : "l"(p));
}

__device__ __forceinline__ void stg_v8(float* __restrict__ p, const float r[8])
{
    asm volatile("st.global.v8.f32 [%0], {%1,%2,%3,%4,%5,%6,%7,%8};"
                 :: "l"(p),
                    "f"(r[0]), "f"(r[1]), "f"(r[2]), "f"(r[3]),
                    "f"(r[4]), "f"(r[5]), "f"(r[6]), "f"(r[7])
                 : "memory");
}

__global__ void __launch_bounds__(256) unpool_kernel_v8(
    const float* __restrict__ upd,
    const float* __restrict__ msk,   // int32 bits, loaded as f32 raw
    float*       __restrict__ out)
{
    const unsigned t = blockIdx.x * 256u + threadIdx.x;   // exact grid

    float u[8], mf[8];
    ldg_v8(upd + (size_t)t * 8u, u);
    ldg_v8(msk + (size_t)t * 8u, mf);

    // sel = dy*2 + dx per channel
    int s[8];
    #pragma unroll
    for (int i = 0; i < 8; ++i) {
        const int m = __float_as_int(mf[i]);
        s[i] = (((m >> 15) & 1) << 1) | ((m >> 7) & 1);
    }

    // t -> (b, h, w, c8): c8 = t&15, w = (t>>4)&127, h = (t>>11)&127, b = t>>18
    const unsigned c8 = t & 15u;
    const unsigned w  = (t >> 4) & 127u;
    const unsigned h  = (t >> 11) & 127u;
    const unsigned b  = t >> 18;

    // Output base in float elements at window position (0,0):
    const unsigned base = ((b * HOUT_ + 2u * h) * WOUT_ + 2u * w) * C_ + 8u * c8;
    const unsigned rowS = WOUT_ * C_;   // 32768 floats: one output row
    const unsigned colS = C_;           // 128 floats: one output column

    #pragma unroll
    for (int p = 0; p < 4; ++p) {       // p = py*2 + px
        float v[8];
        #pragma unroll
        for (int i = 0; i < 8; ++i)
            v[i] = (s[i] == p) ? u[i] : 0.0f;
        const unsigned off = base + (unsigned)(p >> 1) * rowS + (unsigned)(p & 1) * colS;
        stg_v8(out + off, v);
    }
}

extern "C" void kernel_launch(void* const* d_in, const int* in_sizes, int n_in,
                              void* d_out, int out_size)
{
    const float* upd = (const float*)d_in[0];
    const float* msk = (const float*)d_in[1];
    float*       out = (float*)d_out;

    unpool_kernel_v8<<<NTHREADS_ / 256, 256>>>(upd, msk, out);
}

// round 6
// speedup vs baseline: 1.0639x; 1.0639x over previous
#include <cuda_runtime.h>

// MaxUnpooling2D: updates [8,128,128,128] f32, mask [8,128,128,128] i32
// -> out [8,256,256,128] f32.
//
// mask = (y*WOUT + x)*C + f with y=2h+dy, x=2w+dx -> dy=(m>>15)&1, dx=(m>>7)&1.
// Each input element owns its 2x2 output window at its channel: value to (dy,dx),
// zeros to the other 3. Duplicate-free -> no atomics, no init pass, every output
// byte written exactly once. Traffic is at the information floor (402 MB).
//
// R5: R1 structure (proven fastest; v8 and MLP-doubling both disproven) with
// __ldcg input loads: streaming reads have zero reuse, so skip L1 allocation
// and leave the L1 pipeline to stores only.

#define B_    8
#define H_    128
#define W_    128
#define C_    128
#define HOUT_ 256
#define WOUT_ 256

__global__ void __launch_bounds__(256) unpool_kernel(
    const float4* __restrict__ upd4,
    const int4*   __restrict__ msk4,
    float4*       __restrict__ out4)
{
    const unsigned t = blockIdx.x * 256u + threadIdx.x;   // exact grid, no bounds check

    const float4 u = __ldcg(upd4 + t);
    const int4   m = __ldcg(msk4 + t);

    // Per-lane window position code: sel = dy*2 + dx
    const int s0 = (((m.x >> 15) & 1) << 1) | ((m.x >> 7) & 1);
    const int s1 = (((m.y >> 15) & 1) << 1) | ((m.y >> 7) & 1);
    const int s2 = (((m.z >> 15) & 1) << 1) | ((m.z >> 7) & 1);
    const int s3 = (((m.w >> 15) & 1) << 1) | ((m.w >> 7) & 1);

    // t -> (b, h, w, c4): c4 = t&31, w = (t>>5)&127, h = (t>>12)&127, b = t>>19
    const unsigned c4 = t & 31u;
    const unsigned w  = (t >> 5) & 127u;
    const unsigned h  = (t >> 12) & 127u;
    const unsigned b  = t >> 19;

    // Output base (float4 units) of window position (0,0)
    const unsigned base4 = ((b * HOUT_ + 2u * h) * WOUT_ + 2u * w) * (C_ / 4) + c4;
    const unsigned rowS4 = WOUT_ * C_ / 4;   // 8192
    const unsigned colS4 = C_ / 4;           // 32

    #pragma unroll
    for (int p = 0; p < 4; ++p) {            // p = py*2 + px
        float4 v;
        v.x = (s0 == p) ? u.x : 0.0f;
        v.y = (s1 == p) ? u.y : 0.0f;
        v.z = (s2 == p) ? u.z : 0.0f;
        v.w = (s3 == p) ? u.w : 0.0f;
        const unsigned off = base4 + (unsigned)(p >> 1) * rowS4 + (unsigned)(p & 1) * colS4;
        out4[off] = v;
    }
}

extern "C" void kernel_launch(void* const* d_in, const int* in_sizes, int n_in,
                              void* d_out, int out_size)
{
    const float4* upd4 = (const float4*)d_in[0];
    const int4*   msk4 = (const int4*)d_in[1];
    float4*       out4 = (float4*)d_out;

    const unsigned n_threads = (B_ * H_ * W_ * C_) / 4;   // 4,194,304
    unpool_kernel<<<n_threads / 256, 256>>>(upd4, msk4, out4);
}